// round 7
// baseline (speedup 1.0000x reference)
#include <cuda_runtime.h>
#include <math.h>

// Problem constants
#define Bk   4
#define Ck   256
#define BNk  64
#define Hk   128
#define Wk   128
#define HWk  16384
#define K2k  9

// -------- scratch (device globals; no allocations allowed) --------
__device__ float g_z   [Bk * BNk * HWk];   // down-proj output
__device__ float g_off [Bk * 18  * HWk];   // offsets
__device__ float g_mask[Bk * 9   * HWk];   // sigmoid(mask)
__device__ float g_dwT [Ck * BNk];         // down_w transposed: [c][o]
__device__ float g_wbT [BNk * 9 * 32];     // off/mask weights: [(ic*9+tap)*32 + oc], oc<27 valid
__device__ float g_wbBias[32];             // 18 off_b + 9 mask_b + pad
__device__ float g_wdT [9 * BNk * BNk];    // def_w: [(k*64+c)*64 + o]
__device__ float g_sum [Ck];
__device__ float g_sumsq[Ck];

// -------- prep: transpose/repack weights, zero stats --------
__global__ void prep_kernel(const float* __restrict__ down_w,
                            const float* __restrict__ off_w,
                            const float* __restrict__ off_b,
                            const float* __restrict__ mask_w,
                            const float* __restrict__ mask_b,
                            const float* __restrict__ def_w) {
    int i = blockIdx.x * 256 + threadIdx.x;
    if (i < Ck) { g_sum[i] = 0.f; g_sumsq[i] = 0.f; }
    if (i < Ck * BNk) {                 // down_w [64][256] -> [c][o]
        int o = i >> 8, c = i & 255;
        g_dwT[c * 64 + o] = down_w[i];
    }
    if (i < BNk * 9 * 32) {             // off/mask weights
        int oc = i & 31; int rest = i >> 5;
        int tap = rest % 9, ic = rest / 9;
        float v = 0.f;
        if (oc < 18)      v = off_w [(oc * 64 + ic) * 9 + tap];
        else if (oc < 27) v = mask_w[((oc - 18) * 64 + ic) * 9 + tap];
        g_wbT[i] = v;
    }
    if (i < 32) {
        float v = 0.f;
        if (i < 18)      v = off_b[i];
        else if (i < 27) v = mask_b[i - 18];
        g_wbBias[i] = v;
    }
    if (i < BNk * BNk * 9) {            // def_w [o][c][k] -> [(k*64+c)*64+o]
        int o = i / 576, rem = i % 576, c = rem / 9, k = rem % 9;
        g_wdT[(k * 64 + c) * 64 + o] = def_w[i];
    }
}

// -------- kernel A: 1x1 down conv (256->64) --------
__global__ void __launch_bounds__(256) down_kernel(const float* __restrict__ x) {
    int pix = blockIdx.x * 256 + threadIdx.x;
    int b   = blockIdx.y;
    const float* xp = x + (size_t)b * Ck * HWk + pix;

    float acc[64];
#pragma unroll
    for (int o = 0; o < 64; o++) acc[o] = 0.f;

#pragma unroll 4
    for (int c = 0; c < Ck; c++) {
        float xv = __ldg(xp + (size_t)c * HWk);
        const float4* w4 = reinterpret_cast<const float4*>(g_dwT + c * 64);
#pragma unroll
        for (int j = 0; j < 16; j++) {
            float4 w = __ldg(w4 + j);
            acc[4*j+0] += w.x * xv;
            acc[4*j+1] += w.y * xv;
            acc[4*j+2] += w.z * xv;
            acc[4*j+3] += w.w * xv;
        }
    }
    float* zp = g_z + (size_t)b * BNk * HWk + pix;
#pragma unroll
    for (int o = 0; o < 64; o++) zp[(size_t)o * HWk] = acc[o];
}

// -------- kernel B: 3x3 conv -> offsets(18) + sigmoid(mask)(9) --------
__global__ void __launch_bounds__(128) offmask_kernel() {
    __shared__ float s[3][130];
    int tx = threadIdx.x;      // x coordinate
    int y  = blockIdx.x;       // row
    int b  = blockIdx.y;

    float acc[28];
#pragma unroll
    for (int j = 0; j < 28; j++) acc[j] = g_wbBias[j];

    const float* zb = g_z + (size_t)b * BNk * HWk;

#pragma unroll 1
    for (int ic = 0; ic < 64; ic++) {
        const float* zp = zb + (size_t)ic * HWk;
        __syncthreads();
#pragma unroll
        for (int dy = 0; dy < 3; dy++) {
            int yy = y + dy - 1;
            s[dy][tx + 1] = (yy >= 0 && yy < Hk) ? __ldg(zp + yy * Wk + tx) : 0.f;
        }
        if (tx == 0) {
            s[0][0] = 0.f; s[1][0] = 0.f; s[2][0] = 0.f;
            s[0][129] = 0.f; s[1][129] = 0.f; s[2][129] = 0.f;
        }
        __syncthreads();

        const float4* wrow = reinterpret_cast<const float4*>(g_wbT + ic * 9 * 32);
#pragma unroll
        for (int tap = 0; tap < 9; tap++) {
            int ky = tap / 3, kx = tap % 3;
            float zv = s[ky][tx + kx];
#pragma unroll
            for (int j = 0; j < 7; j++) {
                float4 w = __ldg(wrow + tap * 8 + j);
                acc[4*j+0] += w.x * zv;
                acc[4*j+1] += w.y * zv;
                acc[4*j+2] += w.z * zv;
                acc[4*j+3] += w.w * zv;
            }
        }
    }

    int p = y * Wk + tx;
    float* offp = g_off + (size_t)b * 18 * HWk + p;
#pragma unroll
    for (int j = 0; j < 18; j++) offp[(size_t)j * HWk] = acc[j];
    float* mp = g_mask + (size_t)b * 9 * HWk + p;
#pragma unroll
    for (int j = 0; j < 9; j++)
        mp[(size_t)j * HWk] = 1.f / (1.f + __expf(-acc[18 + j]));
}

// -------- kernel C: deform conv + 1x1 up + residual + BN stats --------
__global__ void __launch_bounds__(128) deform_kernel(const float* __restrict__ x,
                                                     const float* __restrict__ def_b,
                                                     const float* __restrict__ up_w,
                                                     float* __restrict__ out) {
    int tx = threadIdx.x;      // x coordinate (one row per block)
    int y  = blockIdx.x;
    int b  = blockIdx.y;
    int p  = y * Wk + tx;

    const float* zb   = g_z    + (size_t)b * BNk * HWk;
    const float* offp = g_off  + (size_t)b * 18  * HWk + p;
    const float* mp   = g_mask + (size_t)b * 9   * HWk + p;

    float acc[64];
#pragma unroll
    for (int o = 0; o < 64; o++) acc[o] = __ldg(def_b + o);

#pragma unroll 1
    for (int k = 0; k < 9; k++) {
        int ky = k / 3, kx = k % 3;
        float dy = __ldg(offp + (size_t)(2 * k)     * HWk);
        float dx = __ldg(offp + (size_t)(2 * k + 1) * HWk);
        float mk = __ldg(mp   + (size_t)k           * HWk);

        float py = dy + (float)(y  + ky - 1);
        float px = dx + (float)(tx + kx - 1);
        float y0f = floorf(py), x0f = floorf(px);
        float wy = py - y0f, wx = px - x0f;
        int y0 = (int)y0f, x0 = (int)x0f;
        int y1 = y0 + 1,   x1 = x0 + 1;
        bool vy0 = (y0 >= 0) && (y0 < Hk), vy1 = (y1 >= 0) && (y1 < Hk);
        bool vx0 = (x0 >= 0) && (x0 < Wk), vx1 = (x1 >= 0) && (x1 < Wk);
        float a00 = (1.f - wy) * (1.f - wx) * mk * ((vy0 && vx0) ? 1.f : 0.f);
        float a01 = (1.f - wy) * wx         * mk * ((vy0 && vx1) ? 1.f : 0.f);
        float a10 = wy         * (1.f - wx) * mk * ((vy1 && vx0) ? 1.f : 0.f);
        float a11 = wy         * wx         * mk * ((vy1 && vx1) ? 1.f : 0.f);
        int yc0 = min(max(y0, 0), Hk - 1), yc1 = min(max(y1, 0), Hk - 1);
        int xc0 = min(max(x0, 0), Wk - 1), xc1 = min(max(x1, 0), Wk - 1);
        int i00 = yc0 * Wk + xc0, i01 = yc0 * Wk + xc1;
        int i10 = yc1 * Wk + xc0, i11 = yc1 * Wk + xc1;

        const float* wk = g_wdT + k * 64 * 64;
#pragma unroll 2
        for (int c = 0; c < 64; c++) {
            const float* zc = zb + (size_t)c * HWk;
            float v = a00 * __ldg(zc + i00) + a01 * __ldg(zc + i01)
                    + a10 * __ldg(zc + i10) + a11 * __ldg(zc + i11);
            const float4* w4 = reinterpret_cast<const float4*>(wk + c * 64);
#pragma unroll
            for (int j = 0; j < 16; j++) {
                float4 w = __ldg(w4 + j);
                acc[4*j+0] += w.x * v;
                acc[4*j+1] += w.y * v;
                acc[4*j+2] += w.z * v;
                acc[4*j+3] += w.w * v;
            }
        }
    }

    // fused 1x1 up conv + residual + BN statistics
    const float* xp = x   + (size_t)b * Ck * HWk + p;
    float*       op = out + (size_t)b * Ck * HWk + p;
#pragma unroll 1
    for (int oc = 0; oc < Ck; oc++) {
        const float4* w4 = reinterpret_cast<const float4*>(up_w + oc * 64);
        float s0 = 0.f, s1 = 0.f, s2 = 0.f, s3 = 0.f;
#pragma unroll
        for (int j = 0; j < 16; j++) {
            float4 w = __ldg(w4 + j);
            s0 += w.x * acc[4*j+0];
            s1 += w.y * acc[4*j+1];
            s2 += w.z * acc[4*j+2];
            s3 += w.w * acc[4*j+3];
        }
        float yv = __ldg(xp + (size_t)oc * HWk) + ((s0 + s1) + (s2 + s3));
        op[(size_t)oc * HWk] = yv;

        float ws = yv, wq = yv * yv;
#pragma unroll
        for (int d = 16; d; d >>= 1) {
            ws += __shfl_xor_sync(0xffffffffu, ws, d);
            wq += __shfl_xor_sync(0xffffffffu, wq, d);
        }
        if ((tx & 31) == 0) {
            atomicAdd(&g_sum[oc], ws);
            atomicAdd(&g_sumsq[oc], wq);
        }
    }
}

// -------- kernel E: BatchNorm (training stats) + SiLU, in place --------
__global__ void __launch_bounds__(256) norm_kernel(float* __restrict__ out,
                                                   const float* __restrict__ gamma,
                                                   const float* __restrict__ beta) {
    const float invN = 1.f / (float)(Bk * HWk);   // 1/65536
    size_t i = (size_t)blockIdx.x * 256 + threadIdx.x;   // float4 index
    int ch = (int)((i >> 12) & 255);                      // 4096 float4 per channel

    float mean = g_sum[ch] * invN;
    float var  = g_sumsq[ch] * invN - mean * mean;
    float r    = rsqrtf(var + 1e-5f);
    float sc   = r * __ldg(gamma + ch);
    float sh   = __ldg(beta + ch) - mean * sc;

    float4* o4 = reinterpret_cast<float4*>(out);
    float4 v = o4[i];
    float h;
    h = v.x * sc + sh; v.x = h / (1.f + __expf(-h));
    h = v.y * sc + sh; v.y = h / (1.f + __expf(-h));
    h = v.z * sc + sh; v.z = h / (1.f + __expf(-h));
    h = v.w * sc + sh; v.w = h / (1.f + __expf(-h));
    o4[i] = v;
}

// -------- launch --------
extern "C" void kernel_launch(void* const* d_in, const int* in_sizes, int n_in,
                              void* d_out, int out_size) {
    const float* x      = (const float*)d_in[0];
    const float* down_w = (const float*)d_in[1];
    const float* off_w  = (const float*)d_in[2];
    const float* off_b  = (const float*)d_in[3];
    const float* mask_w = (const float*)d_in[4];
    const float* mask_b = (const float*)d_in[5];
    const float* def_w  = (const float*)d_in[6];
    const float* def_b  = (const float*)d_in[7];
    const float* up_w   = (const float*)d_in[8];
    const float* gamma  = (const float*)d_in[9];
    const float* beta   = (const float*)d_in[10];
    float* out = (float*)d_out;

    prep_kernel<<<144, 256>>>(down_w, off_w, off_b, mask_w, mask_b, def_w);
    down_kernel<<<dim3(HWk / 256, Bk), 256>>>(x);
    offmask_kernel<<<dim3(Hk, Bk), 128>>>();
    deform_kernel<<<dim3(Hk, Bk), 128>>>(x, def_b, up_w, out);
    norm_kernel<<<(Bk * Ck * HWk) / 4 / 256, 256>>>(out, gamma, beta);
}